// round 5
// baseline (speedup 1.0000x reference)
#include <cuda_runtime.h>
#include <cstdint>
#include <math.h>

// Problem constants: W=num_walks=10, L=walk_length=10, D=64 neighbors.
#define W_WALKS 10
#define L_STEPS 10
#define DNB 64
#define FULLMASK 0xFFFFFFFFu

#define EPSf 1e-10f
#define REL_GAP 1e-4f          // relative guard band (fast errors ~6e-6)

#define MAX_B 8192
#define MAX_WALKS (MAX_B * W_WALKS)                   // 81920

// Precomputed 1/e (e = -log(u), gumbel denominator) for every (step, walk,
// element). 47,185,920 floats = 188.7 MB device scratch.
__device__ float g_inv_e[(size_t)MAX_WALKS * DNB * (L_STEPS - 1)];

struct StepKeys {
    unsigned a[L_STEPS];
    unsigned b[L_STEPS];
};

// ---------------------------------------------------------------------------
// Threefry-2x32 (20 rounds), matching jax._src.prng.threefry2x32 exactly.
// ---------------------------------------------------------------------------
__host__ __device__ __forceinline__ void threefry2x32(
    unsigned k0, unsigned k1, unsigned x0, unsigned x1,
    unsigned& o0, unsigned& o1)
{
    unsigned k2 = k0 ^ k1 ^ 0x1BD11BDAu;
    x0 += k0; x1 += k1;
#if defined(__CUDA_ARCH__)
#define TF_ROT(x, r) __funnelshift_l((x), (x), (r))
#else
#define TF_ROT(x, r) (((x) << (r)) | ((x) >> (32 - (r))))
#endif
#define TF_ROUND(r) { x0 += x1; x1 = TF_ROT(x1, r); x1 ^= x0; }
    TF_ROUND(13) TF_ROUND(15) TF_ROUND(26) TF_ROUND(6)
    x0 += k1; x1 += k2 + 1u;
    TF_ROUND(17) TF_ROUND(29) TF_ROUND(16) TF_ROUND(24)
    x0 += k2; x1 += k0 + 2u;
    TF_ROUND(13) TF_ROUND(15) TF_ROUND(26) TF_ROUND(6)
    x0 += k0; x1 += k1 + 3u;
    TF_ROUND(17) TF_ROUND(29) TF_ROUND(16) TF_ROUND(24)
    x0 += k1; x1 += k2 + 4u;
    TF_ROUND(13) TF_ROUND(15) TF_ROUND(26) TF_ROUND(6)
    x0 += k2; x1 += k0 + 5u;
#undef TF_ROUND
#undef TF_ROT
    o0 = x0; o1 = x1;
}

// Partitionable threefry bits: element i -> counter (0, i), output o0^o1.
__device__ __forceinline__ unsigned random_bits_partitionable(
    unsigned ka, unsigned kb, unsigned idx)
{
    unsigned o0, o1;
    threefry2x32(ka, kb, 0u, idx, o0, o1);
    return o0 ^ o1;
}

// bits -> u in [tiny, 1-2^-23], exactly as jax.random.uniform f32 path.
__device__ __forceinline__ float uniform_from_bits(unsigned bits)
{
    const float tiny = 1.17549435082228750797e-38f;
    unsigned m = (bits >> 9) | 0x3f800000u;
    float u = __uint_as_float(m) - 1.0f;
    u = u + tiny;
    return fmaxf(tiny, u);
}

// Fast 1/e, rel err ~3e-6 everywhere:
//  u >= 0.5: e = 2*atanh(z), z=(1-u)/(1+u) <= 1/3 (1-u exact by Sterbenz);
//            5-term odd series, trunc err (1/3)^10/11 ~ 1.5e-6 rel.
//  u <  0.5: |log u| >= 0.693 so __logf's ~1.6e-7 abs is rel <= 2.4e-7.
__device__ __forceinline__ float inv_e_from_bits(unsigned bits)
{
    float u = uniform_from_bits(bits);
    float lg = -__logf(u);
    float z = __fdividef(1.0f - u, 1.0f + u);
    float y = z * z;
    float p = fmaf(y, fmaf(y, fmaf(y, fmaf(y, 0.111111111f, 0.142857143f),
                                   0.2f), 0.333333333f), 1.0f);
    float e = (u >= 0.5f) ? (2.0f * z * p) : lg;
    return __fdividef(1.0f, e);
}

// Exact gumbel (double-evaluated, correctly-rounded f32 intermediates).
__device__ __forceinline__ float gumbel_exact(unsigned bits)
{
    float u = uniform_from_bits(bits);
    float l1 = (float)log((double)u);
    float l2 = (float)log((double)(-l1));
    return -l2;
}

// ---------------------------------------------------------------------------
// Kernel 1: embarrassingly-parallel gumbel-denominator generation.
// One thread -> two consecutive elements (float2 store). grid.y = step-1.
// ---------------------------------------------------------------------------
__global__ void __launch_bounds__(256)
egen_kernel(int nwalks, StepKeys keys)
{
    const int step = blockIdx.y + 1;
    const unsigned ka = keys.a[step], kb = keys.b[step];
    const unsigned pair = blockIdx.x * blockDim.x + threadIdx.x;
    const unsigned npairs = (unsigned)nwalks * (DNB / 2);
    if (pair >= npairs) return;
    const unsigned n = pair * 2u;
    float i0 = inv_e_from_bits(random_bits_partitionable(ka, kb, n));
    float i1 = inv_e_from_bits(random_bits_partitionable(ka, kb, n + 1u));
    const size_t off = (size_t)(step - 1) * ((size_t)nwalks * DNB) + n;
    *reinterpret_cast<float2*>(g_inv_e + off) = make_float2(i0, i1);
}

// ---------------------------------------------------------------------------
// Kernel 2: sequential walk. One warp per walk, lane owns elements 2L, 2L+1.
// ---------------------------------------------------------------------------
__global__ void __launch_bounds__(256)
walk_kernel(const int* __restrict__ src_nodes,
            const float* __restrict__ cur_times,
            const int* __restrict__ nb_ids,
            const float* __restrict__ nb_times,
            float* __restrict__ out,
            int B, StepKeys keys)
{
    const int gwarp = (int)((blockIdx.x * blockDim.x + threadIdx.x) >> 5);
    const int lane = (int)(threadIdx.x & 31);
    const int nwalks = B * W_WALKS;
    if (gwarp >= nwalks) return;

    const int b = gwarp / W_WALKS;

    int   curr  = src_nodes[b];
    float ctime = cur_times[b];
    bool  alive = true;

    const size_t BWL = (size_t)nwalks * L_STEPS;
    float* out_nodes = out;
    float* out_times = out + BWL;
    float* out_masks = out + 2 * BWL;
    const size_t base = (size_t)gwarp * L_STEPS;

    const float LOG_EPS_EXACT = (float)log((double)EPSf);
    const int d0 = lane << 1;
    const size_t e_walk = (size_t)gwarp * DNB + (size_t)d0;
    const size_t e_step_stride = (size_t)nwalks * DNB;

    if (lane == 0) {
        out_nodes[base] = (float)curr;
        out_times[base] = ctime;
        out_masks[base] = 1.0f;
    }

    #pragma unroll 1
    for (int step = 1; step < L_STEPS; step++) {
        if (alive) {
            const size_t row = (size_t)curr * DNB;
            const int2   ids = reinterpret_cast<const int2*>(nb_ids + row)[lane];
            const float2 ts  = reinterpret_cast<const float2*>(nb_times + row)[lane];
            const float2 iv  = *reinterpret_cast<const float2*>(
                g_inv_e + (size_t)(step - 1) * e_step_stride + e_walk);
            const float t0 = ts.x, t1 = ts.y;

            const bool v0 = (t0 < ctime);
            const bool v1 = (t1 < ctime);

            if (!__any_sync(FULLMASK, v0 || v1)) {
                alive = false;
            } else {
                // Surrogate r_d = (p_d + EPS)/e_d, ctime-centered exps
                // (frame error rigorously <= 2.2e-6 rel). Masked elements
                // (w=0) get r = EPS/e — exactly the reference semantics.
                float w0 = v0 ? __expf((t0 - ctime) * 10.0f) : 0.0f;
                float w1 = v1 ? __expf((t1 - ctime) * 10.0f) : 0.0f;

                float ssum = w0 + w1;
                #pragma unroll
                for (int o = 16; o; o >>= 1)
                    ssum += __shfl_xor_sync(FULLMASK, ssum, o);
                // xor-butterfly: all lanes hold the identical value
                const float rden = __fdividef(1.0f, ssum + EPSf);

                const float r0 = fmaf(w0, rden, EPSf) * iv.x;
                const float r1 = fmaf(w1, rden, EPSf) * iv.y;

                float best = fmaxf(r0, r1);
                #pragma unroll
                for (int o = 16; o; o >>= 1)
                    best = fmaxf(best, __shfl_xor_sync(FULLMASK, best, o));

                const float thr = best * (1.0f - REL_GAP);
                const unsigned b0 = __ballot_sync(FULLMASK, r0 >= thr);
                const unsigned b1 = __ballot_sync(FULLMASK, r1 >= thr);

                int bi;
                if (__popc(b0) + __popc(b1) == 1) {
                    // unique element within the guard band == exact argmax
                    bi = b0 ? ((__ffs(b0) - 1) << 1)
                            : (((__ffs(b1) - 1) << 1) | 1);
                } else {
                    // ---------- EXACT FALLBACK (bit-exact reference) ------
                    const unsigned ka = keys.a[step];
                    const unsigned kb = keys.b[step];
                    const unsigned ebase = (unsigned)gwarp * DNB + (unsigned)d0;

                    float m = fmaxf(t0, t1);
                    #pragma unroll
                    for (int o = 16; o; o >>= 1)
                        m = fmaxf(m, __shfl_xor_sync(FULLMASK, m, o));
                    const float tmax = (m > 0.0f) ? m : 1.0f;

                    float ew0 = 0.0f, ew1 = 0.0f;
                    if (v0) {
                        float s = (float)((double)(t0 - tmax) / (double)0.1f);
                        ew0 = (float)exp((double)s);
                    }
                    if (v1) {
                        float s = (float)((double)(t1 - tmax) / (double)0.1f);
                        ew1 = (float)exp((double)s);
                    }
                    double dsum = (double)ew0 + (double)ew1;
                    #pragma unroll
                    for (int o = 16; o; o >>= 1)
                        dsum += __shfl_xor_sync(FULLMASK, dsum, o);
                    dsum = __shfl_sync(FULLMASK, dsum, 0);
                    const float denom = (float)dsum + EPSf;

                    float sc0, sc1;
                    {
                        float g = gumbel_exact(random_bits_partitionable(ka, kb, ebase));
                        float lp;
                        if (v0) {
                            float p = (float)((double)ew0 / (double)denom);
                            lp = (float)log((double)(p + EPSf));
                        } else lp = LOG_EPS_EXACT;
                        sc0 = lp + g;
                    }
                    {
                        float g = gumbel_exact(random_bits_partitionable(ka, kb, ebase + 1u));
                        float lp;
                        if (v1) {
                            float p = (float)((double)ew1 / (double)denom);
                            lp = (float)log((double)(p + EPSf));
                        } else lp = LOG_EPS_EXACT;
                        sc1 = lp + g;
                    }

                    // argmax, first-index tie-break (jnp.argmax semantics)
                    float bs; int bix;
                    if (sc1 > sc0) { bs = sc1; bix = d0 + 1; }
                    else           { bs = sc0; bix = d0; }
                    #pragma unroll
                    for (int o = 16; o; o >>= 1) {
                        float os = __shfl_xor_sync(FULLMASK, bs, o);
                        int   oi = __shfl_xor_sync(FULLMASK, bix, o);
                        if (os > bs || (os == bs && oi < bix)) { bs = os; bix = oi; }
                    }
                    bi = __shfl_sync(FULLMASK, bix, 0);
                }

                // fetch chosen neighbor from its owner lane (bi warp-uniform)
                const int   slot = (bi & 1);
                const int   nid = __shfl_sync(FULLMASK, slot ? ids.y : ids.x, bi >> 1);
                const float nt  = __shfl_sync(FULLMASK, slot ? t1    : t0,   bi >> 1);

                curr = nid;
                ctime = nt;
            }
        }

        if (lane == 0) {
            out_nodes[base + step] = (float)curr;
            out_times[base + step] = ctime;
            out_masks[base + step] = alive ? 1.0f : 0.0f;
        }
    }
}

// ---------------------------------------------------------------------------
extern "C" void kernel_launch(void* const* d_in, const int* in_sizes, int n_in,
                              void* d_out, int out_size)
{
    const int*   src = (const int*)d_in[0];
    const float* ct  = (const float*)d_in[1];
    const int*   nid = (const int*)d_in[2];
    const float* nt  = (const float*)d_in[3];
    int B = in_sizes[0];
    if (B > MAX_B) B = MAX_B;  // scratch sized for the fixed benchmark shape

    // fold_in(key(42), step) = threefry2x32((0,42), (0,step))
    StepKeys keys;
    for (int s = 0; s < L_STEPS; s++) { keys.a[s] = 0; keys.b[s] = 0; }
    for (int s = 1; s < L_STEPS; s++) {
        unsigned o0, o1;
        threefry2x32(0u, 42u, 0u, (unsigned)s, o0, o1);
        keys.a[s] = o0; keys.b[s] = o1;
    }

    const int nwalks = B * W_WALKS;

    // Kernel 1: generate all 1/e values (step-major layout).
    {
        const unsigned npairs = (unsigned)nwalks * (DNB / 2);
        dim3 grid((npairs + 255) / 256, L_STEPS - 1);
        egen_kernel<<<grid, 256>>>(nwalks, keys);
    }

    // Kernel 2: the walks.
    {
        const int threads = 256;
        const int total_threads = nwalks * 32;
        const int blocks = (total_threads + threads - 1) / threads;
        walk_kernel<<<blocks, threads>>>(src, ct, nid, nt, (float*)d_out, B, keys);
    }
}

// round 6
// speedup vs baseline: 2.1555x; 2.1555x over previous
#include <cuda_runtime.h>
#include <cstdint>
#include <math.h>

// Problem constants: W=num_walks=10, L=walk_length=10, D=64 neighbors.
#define W_WALKS 10
#define L_STEPS 10
#define DNB 64
#define FULLMASK 0xFFFFFFFFu

#define EPSf 1e-10f
#define REL_GAP 1e-4f          // relative guard band (fast errors ~6e-6)

struct StepKeys {
    unsigned a[L_STEPS];
    unsigned b[L_STEPS];
};

// ---------------------------------------------------------------------------
// Threefry-2x32 (20 rounds), matching jax._src.prng.threefry2x32 exactly.
// ---------------------------------------------------------------------------
__host__ __device__ __forceinline__ void threefry2x32(
    unsigned k0, unsigned k1, unsigned x0, unsigned x1,
    unsigned& o0, unsigned& o1)
{
    unsigned k2 = k0 ^ k1 ^ 0x1BD11BDAu;
    x0 += k0; x1 += k1;
#if defined(__CUDA_ARCH__)
#define TF_ROT(x, r) __funnelshift_l((x), (x), (r))
#else
#define TF_ROT(x, r) (((x) << (r)) | ((x) >> (32 - (r))))
#endif
#define TF_ROUND(r) { x0 += x1; x1 = TF_ROT(x1, r); x1 ^= x0; }
    TF_ROUND(13) TF_ROUND(15) TF_ROUND(26) TF_ROUND(6)
    x0 += k1; x1 += k2 + 1u;
    TF_ROUND(17) TF_ROUND(29) TF_ROUND(16) TF_ROUND(24)
    x0 += k2; x1 += k0 + 2u;
    TF_ROUND(13) TF_ROUND(15) TF_ROUND(26) TF_ROUND(6)
    x0 += k0; x1 += k1 + 3u;
    TF_ROUND(17) TF_ROUND(29) TF_ROUND(16) TF_ROUND(24)
    x0 += k1; x1 += k2 + 4u;
    TF_ROUND(13) TF_ROUND(15) TF_ROUND(26) TF_ROUND(6)
    x0 += k2; x1 += k0 + 5u;
#undef TF_ROUND
#undef TF_ROT
    o0 = x0; o1 = x1;
}

// Partitionable threefry bits: element i -> counter (0, i), output o0^o1.
__device__ __forceinline__ unsigned random_bits_partitionable(
    unsigned ka, unsigned kb, unsigned idx)
{
    unsigned o0, o1;
    threefry2x32(ka, kb, 0u, idx, o0, o1);
    return o0 ^ o1;
}

// bits -> u in [tiny, 1-2^-23], exactly as jax.random.uniform f32 path.
__device__ __forceinline__ float uniform_from_bits(unsigned bits)
{
    const float tiny = 1.17549435082228750797e-38f;
    unsigned m = (bits >> 9) | 0x3f800000u;
    float u = __uint_as_float(m) - 1.0f;
    u = u + tiny;
    return fmaxf(tiny, u);
}

// Fast e = -log(u), rel err ~3e-6 everywhere:
//  u >= 0.5: e = 2*atanh(z), z=(1-u)/(1+u) <= 1/3 (1-u exact by Sterbenz);
//            5-term odd series, trunc err (1/3)^10/11 ~ 1.5e-6 rel.
//  u <  0.5: |log u| >= 0.693 so __logf's ~1.6e-7 abs is rel <= 2.4e-7.
__device__ __forceinline__ float e_from_bits(unsigned bits)
{
    float u = uniform_from_bits(bits);
    float lg = -__logf(u);
    float z = __fdividef(1.0f - u, 1.0f + u);
    float y = z * z;
    float p = fmaf(y, fmaf(y, fmaf(y, fmaf(y, 0.111111111f, 0.142857143f),
                                   0.2f), 0.333333333f), 1.0f);
    return (u >= 0.5f) ? (2.0f * z * p) : lg;
}

// Exact gumbel (double-evaluated, correctly-rounded f32 intermediates).
__device__ __forceinline__ float gumbel_exact(unsigned bits)
{
    float u = uniform_from_bits(bits);
    float l1 = (float)log((double)u);
    float l2 = (float)log((double)(-l1));
    return -l2;
}

// ---------------------------------------------------------------------------
// Cold path: bit-exact reference recomputation of one step's argmax.
// Warp-uniform entry (guard condition is uniform). Kept out of the hot loop.
// ---------------------------------------------------------------------------
__device__ __noinline__ int exact_argmax(
    float t0, float t1, bool v0, bool v1, float ctime,
    unsigned ka, unsigned kb, unsigned ebase, int d0)
{
    const float LOG_EPS_EXACT = (float)log((double)EPSf);

    // true tmax over all 64 (unmasked), where(tmax>0, tmax, 1)
    float m = fmaxf(t0, t1);
    #pragma unroll
    for (int o = 16; o; o >>= 1)
        m = fmaxf(m, __shfl_xor_sync(FULLMASK, m, o));
    const float tmax = (m > 0.0f) ? m : 1.0f;

    float ew0 = 0.0f, ew1 = 0.0f;
    if (v0) {
        float s = (float)((double)(t0 - tmax) / (double)0.1f);
        ew0 = (float)exp((double)s);
    }
    if (v1) {
        float s = (float)((double)(t1 - tmax) / (double)0.1f);
        ew1 = (float)exp((double)s);
    }
    double dsum = (double)ew0 + (double)ew1;
    #pragma unroll
    for (int o = 16; o; o >>= 1)
        dsum += __shfl_xor_sync(FULLMASK, dsum, o);
    dsum = __shfl_sync(FULLMASK, dsum, 0);
    const float denom = (float)dsum + EPSf;

    float sc0, sc1;
    {
        float g = gumbel_exact(random_bits_partitionable(ka, kb, ebase));
        float lp;
        if (v0) {
            float p = (float)((double)ew0 / (double)denom);
            lp = (float)log((double)(p + EPSf));
        } else lp = LOG_EPS_EXACT;
        sc0 = lp + g;
    }
    {
        float g = gumbel_exact(random_bits_partitionable(ka, kb, ebase + 1u));
        float lp;
        if (v1) {
            float p = (float)((double)ew1 / (double)denom);
            lp = (float)log((double)(p + EPSf));
        } else lp = LOG_EPS_EXACT;
        sc1 = lp + g;
    }

    // argmax, first-index tie-break (jnp.argmax semantics)
    float bs; int bix;
    if (sc1 > sc0) { bs = sc1; bix = d0 + 1; }
    else           { bs = sc0; bix = d0; }
    #pragma unroll
    for (int o = 16; o; o >>= 1) {
        float os = __shfl_xor_sync(FULLMASK, bs, o);
        int   oi = __shfl_xor_sync(FULLMASK, bix, o);
        if (os > bs || (os == bs && oi < bix)) { bs = os; bix = oi; }
    }
    return __shfl_sync(FULLMASK, bix, 0);
}

// ---------------------------------------------------------------------------
// One warp per walk. Lane L owns elements d=2L and d=2L+1 (vector loads).
// ---------------------------------------------------------------------------
__global__ void __launch_bounds__(256)
walk_kernel(const int* __restrict__ src_nodes,
            const float* __restrict__ cur_times,
            const int* __restrict__ nb_ids,
            const float* __restrict__ nb_times,
            float* __restrict__ out,
            int B, StepKeys keys)
{
    const int gwarp = (int)((blockIdx.x * blockDim.x + threadIdx.x) >> 5);
    const int lane = (int)(threadIdx.x & 31);
    const int nwalks = B * W_WALKS;
    if (gwarp >= nwalks) return;

    const int b = gwarp / W_WALKS;

    int   curr  = src_nodes[b];
    float ctime = cur_times[b];
    bool  alive = true;

    const size_t BWL = (size_t)nwalks * L_STEPS;
    float* out_nodes = out;
    float* out_times = out + BWL;
    float* out_masks = out + 2 * BWL;
    const size_t base = (size_t)gwarp * L_STEPS;

    const int d0 = lane << 1;
    const unsigned ebase = (unsigned)gwarp * DNB + (unsigned)d0;

    if (lane == 0) {
        out_nodes[base] = (float)curr;
        out_times[base] = ctime;
        out_masks[base] = 1.0f;
    }

    #pragma unroll 1
    for (int step = 1; step < L_STEPS; step++) {
        if (alive) {
            const size_t row = (size_t)curr * DNB;
            const int2   ids = reinterpret_cast<const int2*>(nb_ids + row)[lane];
            const float2 ts  = reinterpret_cast<const float2*>(nb_times + row)[lane];
            const float t0 = ts.x, t1 = ts.y;

            const bool v0 = (t0 < ctime);
            const bool v1 = (t1 < ctime);

            if (!__any_sync(FULLMASK, v0 || v1)) {
                alive = false;
            } else {
                const unsigned ka = keys.a[step];
                const unsigned kb = keys.b[step];

                // Gumbel denominators (independent of loads -> compiler can
                // overlap this 140-inst ALU block with the gather latency).
                const float e0 = e_from_bits(random_bits_partitionable(ka, kb, ebase));
                const float e1 = e_from_bits(random_bits_partitionable(ka, kb, ebase + 1u));

                // Surrogate r_d = (p_d + EPS)/e_d, ctime-centered exps
                // (frame error rigorously <= 2.2e-6 rel). Masked elements
                // (w=0) get r = EPS/e — exactly the reference semantics.
                float w0 = v0 ? __expf((t0 - ctime) * 10.0f) : 0.0f;
                float w1 = v1 ? __expf((t1 - ctime) * 10.0f) : 0.0f;

                float ssum = w0 + w1;
                #pragma unroll
                for (int o = 16; o; o >>= 1)
                    ssum += __shfl_xor_sync(FULLMASK, ssum, o);
                // xor-butterfly: all lanes hold the identical value
                const float rden = __fdividef(1.0f, ssum + EPSf);

                const float r0 = __fdividef(fmaf(w0, rden, EPSf), e0);
                const float r1 = __fdividef(fmaf(w1, rden, EPSf), e1);

                float best = fmaxf(r0, r1);
                #pragma unroll
                for (int o = 16; o; o >>= 1)
                    best = fmaxf(best, __shfl_xor_sync(FULLMASK, best, o));

                const float thr = best * (1.0f - REL_GAP);
                const unsigned b0 = __ballot_sync(FULLMASK, r0 >= thr);
                const unsigned b1 = __ballot_sync(FULLMASK, r1 >= thr);

                int bi;
                if (__popc(b0) + __popc(b1) == 1) {
                    // unique element within the guard band == exact argmax
                    bi = b0 ? ((__ffs(b0) - 1) << 1)
                            : (((__ffs(b1) - 1) << 1) | 1);
                } else {
                    bi = exact_argmax(t0, t1, v0, v1, ctime, ka, kb, ebase, d0);
                }

                // fetch chosen neighbor from its owner lane (bi warp-uniform)
                const int   slot = (bi & 1);
                const int   nid = __shfl_sync(FULLMASK, slot ? ids.y : ids.x, bi >> 1);
                const float nt  = __shfl_sync(FULLMASK, slot ? t1    : t0,   bi >> 1);

                curr = nid;
                ctime = nt;
            }
        }

        if (lane == 0) {
            out_nodes[base + step] = (float)curr;
            out_times[base + step] = ctime;
            out_masks[base + step] = alive ? 1.0f : 0.0f;
        }
    }
}

// ---------------------------------------------------------------------------
extern "C" void kernel_launch(void* const* d_in, const int* in_sizes, int n_in,
                              void* d_out, int out_size)
{
    const int*   src = (const int*)d_in[0];
    const float* ct  = (const float*)d_in[1];
    const int*   nid = (const int*)d_in[2];
    const float* nt  = (const float*)d_in[3];
    const int B = in_sizes[0];

    // fold_in(key(42), step) = threefry2x32((0,42), (0,step))
    StepKeys keys;
    for (int s = 0; s < L_STEPS; s++) { keys.a[s] = 0; keys.b[s] = 0; }
    for (int s = 1; s < L_STEPS; s++) {
        unsigned o0, o1;
        threefry2x32(0u, 42u, 0u, (unsigned)s, o0, o1);
        keys.a[s] = o0; keys.b[s] = o1;
    }

    const int nwalks = B * W_WALKS;
    const int threads = 256;
    const int total_threads = nwalks * 32;
    const int blocks = (total_threads + threads - 1) / threads;

    walk_kernel<<<blocks, threads>>>(src, ct, nid, nt, (float*)d_out, B, keys);
}